// round 13
// baseline (speedup 1.0000x reference)
#include <cuda_runtime.h>
#include <cstdint>

// InteractionArch: out[b] = concat(dense[b] (128), sparse[b]·dense[b] (26),
//                                  triu_{k=1}(sparse[b]·sparse[b]^T) (325))
// B=16384, F=26, D=128, out stride 479 fp32 (row base only 4B-aligned).
//
// R13: R12 (bulk-DMA fill, 7x7 reg tiles, 3 rows/block, FFMA2, conflict-free
// rotated LDS.128) + 2-warp k-split per block: warp w computes quad-steps
// [16w,16w+16). Partials combined once through (dead) Xs smem, warp 0
// scatters. 43KB smem, <=204 regs -> 5 blocks x 2 warps = 10 warps/SM.

#define B_TOT 16384
#define NF 26
#define DD 128
#define NV 28
#define NQ 32            // float4 quads per vector
#define HQ 16            // quad-steps per warp (k-split)
#define OUT_STRIDE 479
#define RPW 3
#define SP_BYTES (NF * DD * 4)   // 13312
#define DN_BYTES (DD * 4)        // 512

__device__ __forceinline__ uint32_t smem_u32(const void* p) {
    uint32_t a;
    asm("{ .reg .u64 t; cvta.to.shared.u64 t, %1; cvt.u32.u64 %0, t; }" : "=r"(a) : "l"(p));
    return a;
}
__device__ __forceinline__ void bulk_ld(uint32_t dst, const void* src,
                                        uint32_t bytes, uint32_t mbar) {
    asm volatile(
        "cp.async.bulk.shared::cta.global.mbarrier::complete_tx::bytes "
        "[%0], [%1], %2, [%3];"
        :: "r"(dst), "l"(src), "r"(bytes), "r"(mbar) : "memory");
}
// packed f32x2 fma: acc(2xf32) += a(2xf32) * b(2xf32)
__device__ __forceinline__ void ffma2(unsigned long long& acc,
                                      unsigned long long a,
                                      unsigned long long b) {
    asm("fma.rn.f32x2 %0, %1, %2, %0;" : "+l"(acc) : "l"(a), "l"(b));
}

__global__ void __launch_bounds__(64, 5) interact_kernel(
    const float* __restrict__ dense,
    const float* __restrict__ sparse,
    float* __restrict__ out)
{
    __shared__ float Xs[RPW][NV][DD];                  // 43008 B
    __shared__ __align__(8) unsigned long long mbar_s;

    const int tid  = threadIdx.x;
    const int wid  = tid >> 5;
    const int lane = tid & 31;
    const int b0   = blockIdx.x * RPW;
    const uint32_t mbar = smem_u32(&mbar_s);

    // ---- mbarrier init must be visible before anyone polls ----
    if (tid == 0) {
        asm volatile("mbarrier.init.shared.b64 [%0], %1;" :: "r"(mbar), "r"(1u) : "memory");
    }
    __syncthreads();

    // ---- issue bulk loads (thread 0) ----
    if (tid == 0) {
        int nvalid = 0;
        #pragma unroll
        for (int r = 0; r < RPW; r++)
            if (b0 + r < B_TOT) nvalid++;
        const uint32_t tx = (uint32_t)nvalid * (SP_BYTES + DN_BYTES);
        asm volatile("mbarrier.arrive.expect_tx.shared.b64 _, [%0], %1;"
                     :: "r"(mbar), "r"(tx) : "memory");
        #pragma unroll
        for (int r = 0; r < RPW; r++) {
            const int b = b0 + r;
            if (b < B_TOT) {
                bulk_ld(smem_u32(&Xs[r][0][0]),  sparse + (size_t)b * NF * DD,
                        SP_BYTES, mbar);
                bulk_ld(smem_u32(&Xs[r][26][0]), dense + (size_t)b * DD,
                        DN_BYTES, mbar);
            }
        }
    }

    // ---- overlap with DMA: zero pad row 27 (96 float4 over 64 thr) ----
    {
        const float4 z = make_float4(0.f, 0.f, 0.f, 0.f);
        int idx = tid;
        reinterpret_cast<float4*>(&Xs[idx / 32][27][0])[idx & 31] = z;
        idx = tid + 64;
        if (idx < RPW * 32)
            reinterpret_cast<float4*>(&Xs[idx / 32][27][0])[idx & 31] = z;
    }
    // ---- dense passthrough, rows split across the 2 warps ----
    for (int r = wid; r < RPW; r += 2) {
        const int b = b0 + r;
        if (b >= B_TOT) break;
        float4 dv = reinterpret_cast<const float4*>(dense + (size_t)b * DD)[lane];
        float* ob = out + (size_t)b * OUT_STRIDE;
        ob[4 * lane + 0] = dv.x;
        ob[4 * lane + 1] = dv.y;
        ob[4 * lane + 2] = dv.z;
        ob[4 * lane + 3] = dv.w;
    }

    // ---- wait for DMA completion (parity 0) ----
    {
        uint32_t done;
        asm volatile(
            "{\n\t.reg .pred p;\n\t"
            "mbarrier.try_wait.parity.acquire.cta.shared::cta.b64 p, [%1], %2;\n\t"
            "selp.b32 %0, 1, 0, p;\n\t}"
            : "=r"(done) : "r"(mbar), "r"(0u) : "memory");
        if (!done) {
            asm volatile(
                "{\n\t.reg .pred P1;\n\t"
                "WL_%=:\n\t"
                "mbarrier.try_wait.parity.acquire.cta.shared::cta.b64 P1, [%0], %1, 0x989680;\n\t"
                "@P1 bra.uni WD_%=;\n\t"
                "bra.uni WL_%=;\n\t"
                "WD_%=:\n\t}"
                :: "r"(mbar), "r"(0u) : "memory");
        }
    }

    // ---- lane -> (row, tile): 3 rows x 10 upper-tri 7x7 tiles ----
    const int r  = lane / 10;                  // 0..2 (lanes 30,31 idle)
    const int t  = lane - r * 10;              // 0..9
    const int bc = b0 + r;
    const bool active = (lane < 30) && (bc < B_TOT);

    const int ti = (t < 4) ? 0 : (t < 7) ? 1 : (t < 9) ? 2 : 3;
    const int tj = (t < 4) ? t : (t < 7) ? t - 3 : (t < 9) ? t - 5 : 3;

    unsigned long long acc2[7][7];             // packed f32x2 partial sums
    #pragma unroll
    for (int ii = 0; ii < 7; ii++)
        #pragma unroll
        for (int jj = 0; jj < 7; jj++)
            acc2[ii][jj] = 0ULL;

    if (active) {
        const ulonglong2* __restrict__ pi2 =
            reinterpret_cast<const ulonglong2*>(&Xs[r][7 * ti][0]);
        const ulonglong2* __restrict__ pj2 =
            reinterpret_cast<const ulonglong2*>(&Xs[r][7 * tj][0]);

        // k-split: warp w covers quad-steps [16w, 16w+16). Rotation keeps
        // each 8-lane phase on distinct bank-quads (row stride 128 floats).
        const int k0 = HQ * wid;
        #pragma unroll 4
        for (int kk = 0; kk < HQ; kk++) {
            const int kq = (k0 + kk + lane) & (NQ - 1);
            ulonglong2 xi[7], xj[7];
            #pragma unroll
            for (int ii = 0; ii < 7; ii++) xi[ii] = pi2[ii * NQ + kq];
            #pragma unroll
            for (int jj = 0; jj < 7; jj++) xj[jj] = pj2[jj * NQ + kq];
            #pragma unroll
            for (int ii = 0; ii < 7; ii++)
                #pragma unroll
                for (int jj = 0; jj < 7; jj++) {
                    ffma2(acc2[ii][jj], xi[ii].x, xj[jj].x);
                    ffma2(acc2[ii][jj], xi[ii].y, xj[jj].y);
                }
        }
    }

    // ---- combine the two warps' partials through (dead) Xs ----
    __syncthreads();                           // everyone done reading Xs
    unsigned long long* part = reinterpret_cast<unsigned long long*>(&Xs[0][0][0]);
    if (wid == 1 && active) {
        #pragma unroll
        for (int ii = 0; ii < 7; ii++)
            #pragma unroll
            for (int jj = 0; jj < 7; jj++)
                part[lane * 49 + ii * 7 + jj] = acc2[ii][jj];
    }
    __syncthreads();

    if (wid == 0 && active) {
        float* ob = out + (size_t)bc * OUT_STRIDE;
        #pragma unroll
        for (int ii = 0; ii < 7; ii++) {
            #pragma unroll
            for (int jj = 0; jj < 7; jj++) {
                const int i = 7 * ti + ii;
                const int j = 7 * tj + jj;
                if (i < j && j <= 26) {
                    unsigned long long o = part[lane * 49 + ii * 7 + jj];
                    float2 p0 = *reinterpret_cast<float2*>(&acc2[ii][jj]);
                    float2 p1 = *reinterpret_cast<float2*>(&o);
                    float v = (p0.x + p1.x) + (p0.y + p1.y);
                    int dst;
                    if (j == 26) {
                        dst = 128 + i;                                        // sparse·dense
                    } else {
                        dst = 154 + i * 25 - (i * (i - 1)) / 2 + (j - i - 1); // pair
                    }
                    ob[dst] = v;
                }
            }
        }
    }
}

extern "C" void kernel_launch(void* const* d_in, const int* in_sizes, int n_in,
                              void* d_out, int out_size)
{
    (void)n_in; (void)out_size;
    const float* a = (const float*)d_in[0];
    const float* b = (const float*)d_in[1];
    // dense has B*D = 2,097,152 elems; sparse has B*F*D = 54,525,952 elems.
    const float* dense  = (in_sizes[0] < in_sizes[1]) ? a : b;
    const float* sparse = (in_sizes[0] < in_sizes[1]) ? b : a;

    const int grid = (B_TOT + RPW - 1) / RPW;
    interact_kernel<<<grid, 64>>>(dense, sparse, (float*)d_out);
}

// round 14
// speedup vs baseline: 1.0487x; 1.0487x over previous
#include <cuda_runtime.h>
#include <cstdint>

// InteractionArch: out[b] = concat(dense[b] (128), sparse[b]·dense[b] (26),
//                                  triu_{k=1}(sparse[b]·sparse[b]^T) (325))
// B=16384, F=26, D=128, out stride 479 fp32 (row base only 4B-aligned).
//
// R14: R12 (bulk-DMA fill, 7x7 reg tiles, 3 rows/block, 1 warp, FFMA2,
// conflict-free rotated LDS.128, 5 blocks/SM) + explicit 2-stage operand
// software pipeline: xi/xj double-buffered in registers so qstep k+1's LDS
// overlap qstep k's FFMA2 stream. No launch_bounds reg cap (5 blocks are
// smem-limited; reg budget 409/thread).

#define B_TOT 16384
#define NF 26
#define DD 128
#define NV 28
#define NQ 32            // float4 quads per vector
#define OUT_STRIDE 479
#define RPW 3
#define SP_BYTES (NF * DD * 4)   // 13312
#define DN_BYTES (DD * 4)        // 512

__device__ __forceinline__ uint32_t smem_u32(const void* p) {
    uint32_t a;
    asm("{ .reg .u64 t; cvta.to.shared.u64 t, %1; cvt.u32.u64 %0, t; }" : "=r"(a) : "l"(p));
    return a;
}
__device__ __forceinline__ void bulk_ld(uint32_t dst, const void* src,
                                        uint32_t bytes, uint32_t mbar) {
    asm volatile(
        "cp.async.bulk.shared::cta.global.mbarrier::complete_tx::bytes "
        "[%0], [%1], %2, [%3];"
        :: "r"(dst), "l"(src), "r"(bytes), "r"(mbar) : "memory");
}
// packed f32x2 fma: acc(2xf32) += a(2xf32) * b(2xf32)
__device__ __forceinline__ void ffma2(unsigned long long& acc,
                                      unsigned long long a,
                                      unsigned long long b) {
    asm("fma.rn.f32x2 %0, %1, %2, %0;" : "+l"(acc) : "l"(a), "l"(b));
}

__global__ void __launch_bounds__(32) interact_kernel(
    const float* __restrict__ dense,
    const float* __restrict__ sparse,
    float* __restrict__ out)
{
    __shared__ float Xs[RPW][NV][DD];                  // 43008 B
    __shared__ __align__(8) unsigned long long mbar_s;

    const int lane = threadIdx.x;
    const int b0   = blockIdx.x * RPW;
    const uint32_t mbar = smem_u32(&mbar_s);

    // ---- init mbarrier, issue bulk loads (thread 0) ----
    if (lane == 0) {
        asm volatile("mbarrier.init.shared.b64 [%0], %1;" :: "r"(mbar), "r"(1u) : "memory");
    }
    __syncwarp();
    if (lane == 0) {
        int nvalid = 0;
        #pragma unroll
        for (int r = 0; r < RPW; r++)
            if (b0 + r < B_TOT) nvalid++;
        const uint32_t tx = (uint32_t)nvalid * (SP_BYTES + DN_BYTES);
        asm volatile("mbarrier.arrive.expect_tx.shared.b64 _, [%0], %1;"
                     :: "r"(mbar), "r"(tx) : "memory");
        #pragma unroll
        for (int r = 0; r < RPW; r++) {
            const int b = b0 + r;
            if (b < B_TOT) {
                bulk_ld(smem_u32(&Xs[r][0][0]),  sparse + (size_t)b * NF * DD,
                        SP_BYTES, mbar);
                bulk_ld(smem_u32(&Xs[r][26][0]), dense + (size_t)b * DD,
                        DN_BYTES, mbar);
            }
        }
    }

    // ---- overlap with DMA: zero pad row 27 + dense passthrough ----
    #pragma unroll
    for (int r = 0; r < RPW; r++) {
        reinterpret_cast<float4*>(&Xs[r][27][0])[lane] = make_float4(0.f, 0.f, 0.f, 0.f);
    }
    #pragma unroll
    for (int r = 0; r < RPW; r++) {
        const int b = b0 + r;
        if (b >= B_TOT) break;
        float4 dv = reinterpret_cast<const float4*>(dense + (size_t)b * DD)[lane];
        float* ob = out + (size_t)b * OUT_STRIDE;
        ob[4 * lane + 0] = dv.x;
        ob[4 * lane + 1] = dv.y;
        ob[4 * lane + 2] = dv.z;
        ob[4 * lane + 3] = dv.w;
    }

    // ---- wait for DMA completion (parity 0) ----
    {
        uint32_t done;
        asm volatile(
            "{\n\t.reg .pred p;\n\t"
            "mbarrier.try_wait.parity.acquire.cta.shared::cta.b64 p, [%1], %2;\n\t"
            "selp.b32 %0, 1, 0, p;\n\t}"
            : "=r"(done) : "r"(mbar), "r"(0u) : "memory");
        if (!done) {
            asm volatile(
                "{\n\t.reg .pred P1;\n\t"
                "WL_%=:\n\t"
                "mbarrier.try_wait.parity.acquire.cta.shared::cta.b64 P1, [%0], %1, 0x989680;\n\t"
                "@P1 bra.uni WD_%=;\n\t"
                "bra.uni WL_%=;\n\t"
                "WD_%=:\n\t}"
                :: "r"(mbar), "r"(0u) : "memory");
        }
    }
    __syncwarp();

    // ---- lane -> (row, tile): 3 rows x 10 upper-tri 7x7 tiles ----
    const int r  = lane / 10;                  // 0..2 (lanes 30,31 idle)
    const int t  = lane - r * 10;              // 0..9
    const int bc = b0 + r;
    const bool active = (lane < 30) && (bc < B_TOT);

    const int ti = (t < 4) ? 0 : (t < 7) ? 1 : (t < 9) ? 2 : 3;
    const int tj = (t < 4) ? t : (t < 7) ? t - 3 : (t < 9) ? t - 5 : 3;

    if (active) {
        unsigned long long acc2[7][7];         // packed f32x2 partial sums
        #pragma unroll
        for (int ii = 0; ii < 7; ii++)
            #pragma unroll
            for (int jj = 0; jj < 7; jj++)
                acc2[ii][jj] = 0ULL;

        const ulonglong2* __restrict__ pi2 =
            reinterpret_cast<const ulonglong2*>(&Xs[r][7 * ti][0]);
        const ulonglong2* __restrict__ pj2 =
            reinterpret_cast<const ulonglong2*>(&Xs[r][7 * tj][0]);

        // 2-stage operand pipeline: load set s^1 for qstep kk+1 while FMAs
        // consume set s. Conflict-free: bank-quad (kk+lane)&7 distinct within
        // each 8-lane phase group (row stride 128 floats).
        ulonglong2 xi[2][7], xj[2][7];

        #pragma unroll
        for (int ii = 0; ii < 7; ii++) xi[0][ii] = pi2[ii * NQ + (lane & (NQ - 1))];
        #pragma unroll
        for (int jj = 0; jj < 7; jj++) xj[0][jj] = pj2[jj * NQ + (lane & (NQ - 1))];

        #pragma unroll 4
        for (int kk = 0; kk < NQ; kk++) {
            const int s = kk & 1;
            if (kk + 1 < NQ) {
                const int kq1 = (kk + 1 + lane) & (NQ - 1);
                #pragma unroll
                for (int ii = 0; ii < 7; ii++) xi[s ^ 1][ii] = pi2[ii * NQ + kq1];
                #pragma unroll
                for (int jj = 0; jj < 7; jj++) xj[s ^ 1][jj] = pj2[jj * NQ + kq1];
            }
            #pragma unroll
            for (int ii = 0; ii < 7; ii++)
                #pragma unroll
                for (int jj = 0; jj < 7; jj++) {
                    ffma2(acc2[ii][jj], xi[s][ii].x, xj[s][jj].x);
                    ffma2(acc2[ii][jj], xi[s][ii].y, xj[s][jj].y);
                }
        }

        // ---- epilogue: horizontal add + scatter (i<j, j<=26) ----
        float* ob = out + (size_t)bc * OUT_STRIDE;
        #pragma unroll
        for (int ii = 0; ii < 7; ii++) {
            #pragma unroll
            for (int jj = 0; jj < 7; jj++) {
                const int i = 7 * ti + ii;
                const int j = 7 * tj + jj;
                if (i < j && j <= 26) {
                    float2 p = *reinterpret_cast<float2*>(&acc2[ii][jj]);
                    float v = p.x + p.y;
                    int dst;
                    if (j == 26) {
                        dst = 128 + i;                                        // sparse·dense
                    } else {
                        dst = 154 + i * 25 - (i * (i - 1)) / 2 + (j - i - 1); // pair
                    }
                    ob[dst] = v;
                }
            }
        }
    }
}

extern "C" void kernel_launch(void* const* d_in, const int* in_sizes, int n_in,
                              void* d_out, int out_size)
{
    (void)n_in; (void)out_size;
    const float* a = (const float*)d_in[0];
    const float* b = (const float*)d_in[1];
    // dense has B*D = 2,097,152 elems; sparse has B*F*D = 54,525,952 elems.
    const float* dense  = (in_sizes[0] < in_sizes[1]) ? a : b;
    const float* sparse = (in_sizes[0] < in_sizes[1]) ? b : a;

    const int grid = (B_TOT + RPW - 1) / RPW;
    interact_kernel<<<grid, 32>>>(dense, sparse, (float*)d_out);
}